// round 14
// baseline (speedup 1.0000x reference)
#include <cuda_runtime.h>
#include <cuda_bf16.h>

// PropagationOnly_SharedPixel: 12 iterations of
//   u <- tanh(scalar * (const + w[i] * sum_{3x3}(u)))
// on a 64x64 grid, batch 128. The dense matvec is a 9-point box stencil
// (hiddenWeight = 3x3 grid adjacency row-scaled by w) -> hiddenWeight unused.
//
// FINAL (= R7, best measured at 8.64us kernel time, twice): 512 threads,
// warp = 4 rows, lane = 2 adjacent cols. Halo rows via double-buffered SMEM,
// horizontal exchange via shuffles, f32x2 packed math, interior/boundary
// phase split (interior rows 1,2 are register-only and overlap the
// deferred-blocking barrier), 4-pixel shared-rcp tanh, 1 __syncthreads/iter.

#define NSIDE 64
#define HPIX  4096
#define ITERS 12
#define SROWS 34           // 32 stored boundary rows + zero row above/below

__device__ __forceinline__ float ex2_approx(float x) {
    float y; asm("ex2.approx.f32 %0, %1;" : "=f"(y) : "f"(x)); return y;
}
__device__ __forceinline__ float rcp_approx(float x) {
    float y; asm("rcp.approx.f32 %0, %1;" : "=f"(y) : "f"(x)); return y;
}
__device__ __forceinline__ float2 add2(float2 a, float2 b) {
    unsigned long long ua, ub, ur;
    ua = *reinterpret_cast<unsigned long long*>(&a);
    ub = *reinterpret_cast<unsigned long long*>(&b);
    asm("add.rn.f32x2 %0, %1, %2;" : "=l"(ur) : "l"(ua), "l"(ub));
    return *reinterpret_cast<float2*>(&ur);
}
__device__ __forceinline__ float2 fma2(float2 a, float2 b, float2 c) {
    unsigned long long ua, ub, uc, ur;
    ua = *reinterpret_cast<unsigned long long*>(&a);
    ub = *reinterpret_cast<unsigned long long*>(&b);
    uc = *reinterpret_cast<unsigned long long*>(&c);
    asm("fma.rn.f32x2 %0, %1, %2, %3;" : "=l"(ur) : "l"(ua), "l"(ub), "l"(uc));
    return *reinterpret_cast<float2*>(&ur);
}

struct Pair { float2 lo, hi; };

// tanh for 4 pixels (two packed pairs) with ONE rcp:
// 1/d_i reconstructed from prefix/suffix products around rcp(d0*d1*d2*d3).
__device__ __forceinline__ Pair tanh4(float2 ta, float2 tb,
                                      float2 mneg2, float2 one2)
{
    const float a0 = fminf(ta.x, 24.0f), a1 = fminf(ta.y, 24.0f);
    const float b0 = fminf(tb.x, 24.0f), b1 = fminf(tb.y, 24.0f);
    const float dA0 = 1.0f + ex2_approx(a0);
    const float dA1 = 1.0f + ex2_approx(a1);
    const float dB0 = 1.0f + ex2_approx(b0);
    const float dB1 = 1.0f + ex2_approx(b1);
    const float pA = dA0 * dA1;                 // <= 2^50, finite
    const float pB = dB0 * dB1;
    const float R  = rcp_approx(pA * pB);       // <= 2^100, finite
    const float RA = R * pB;                    // = 1/pA
    const float RB = R * pA;                    // = 1/pB
    float2 iA, iB;
    iA.x = RA * dA1;  iA.y = RA * dA0;          // 1/dA0, 1/dA1
    iB.x = RB * dB1;  iB.y = RB * dB0;
    Pair r;
    r.lo = fma2(mneg2, iA, one2);               // tanh = 1 - 2/d
    r.hi = fma2(mneg2, iB, one2);
    return r;
}

__global__ void __launch_bounds__(512, 1)
prop_stencil_kernel(const float* __restrict__ X,
                    const float* __restrict__ pred,
                    const float* __restrict__ w,
                    const float* __restrict__ a,
                    const float* __restrict__ bias,
                    const float* __restrict__ scalar_p,
                    float* __restrict__ out)
{
    __shared__ float buf[2][SROWS][NSIDE];      // 2 x 34 x 64 x 4 = 17.4 KB

    const int b    = blockIdx.x;
    const int tid  = threadIdx.x;
    const int wid  = tid >> 5;                  // 0..15 -> rows 4w..4w+3
    const int lane = tid & 31;                  // -> cols 2l, 2l+1
    const int r0   = wid << 2;
    const int c0   = lane << 1;

    // Zero rows 0 and 33 of both buffers (256 words).
    if (tid < 256) {
        const int bb = tid >> 7;
        const int rr = ((tid >> 6) & 1) ? (SROWS - 1) : 0;
        buf[bb][rr][tid & 63] = 0.0f;
    }

    const float K = scalar_p[0] * 2.88539008177793f;   // 2*scalar*log2(e)

    const float2* Xb = (const float2*)(X    + (size_t)b * HPIX);
    const float2* Pb = (const float2*)(pred + (size_t)b * HPIX);
    const float2* w2 = (const float2*)w;
    const float2* a2 = (const float2*)a;
    const float2* b2 = (const float2*)bias;

    // 8 pixels per thread, packed: u[row].{x,y} = cols c0, c0+1.
    float2 u[4], cs[4], wk[4];
    #pragma unroll
    for (int k = 0; k < 4; k++) {
        const int i = (r0 + k) * 32 + lane;
        const float2 p  = Pb[i];
        const float2 x  = Xb[i];
        const float2 ww = w2[i];
        const float2 aa = a2[i];
        const float2 bs = b2[i];
        u[k] = p;
        cs[k].x = (((p.x == -1.0f) ? 0.0f : p.x) + bs.x + aa.x * x.x) * K;
        cs[k].y = (((p.y == -1.0f) ? 0.0f : p.y) + bs.y + aa.y * x.y) * K;
        wk[k].x = ww.x * K;  wk[k].y = ww.y * K;
    }

    // Border masks packed: s = {VL,VR}*{zL,zR} + {h,h}.
    const float2 zLR   = make_float2((lane == 0) ? 0.0f : 1.0f,
                                     (lane == 31) ? 0.0f : 1.0f);
    const float2 mneg2 = make_float2(-2.0f, -2.0f);
    const float2 one2  = make_float2( 1.0f,  1.0f);

    // Seed buffer 0's boundary rows: warp w stores row 4w -> slot 2w+1,
    // row 4w+3 -> slot 2w+2; reads top halo (4w-1) from slot 2w, bottom halo
    // (4w+4) from slot 2w+3; slots 0 and 33 are the zero border.
    *(float2*)&buf[0][2 * wid + 1][c0] = u[0];
    *(float2*)&buf[0][2 * wid + 2][c0] = u[3];
    __syncthreads();        // covers zero-fill + seeding, once.

    #pragma unroll
    for (int it = 0; it < ITERS; it++) {
        const float (*S)[NSIDE] = buf[it & 1];

        // ---- Phase 1: interior rows 1,2 — register-only stencil. Placed
        // before any SMEM access so it issues past the (deferred-blocking)
        // barrier while other warps arrive. ----
        const float2 m01 = add2(u[0], u[1]);
        const float2 m23 = add2(u[2], u[3]);
        const float2 V1  = add2(m01, u[2]);     // rows 0+1+2
        const float2 V2  = add2(u[1], m23);     // rows 1+2+3

        const float VL1 = __shfl_up_sync(0xffffffffu, V1.y, 1);
        const float VR1 = __shfl_down_sync(0xffffffffu, V1.x, 1);
        const float VL2 = __shfl_up_sync(0xffffffffu, V2.y, 1);
        const float VR2 = __shfl_down_sync(0xffffffffu, V2.x, 1);
        const float h1 = V1.x + V1.y;
        const float h2 = V2.x + V2.y;
        const float2 s1 = fma2(make_float2(VL1, VR1), zLR, make_float2(h1, h1));
        const float2 s2 = fma2(make_float2(VL2, VR2), zLR, make_float2(h2, h2));
        const float2 t1 = fma2(wk[1], s1, cs[1]);
        const float2 t2 = fma2(wk[2], s2, cs[2]);
        const Pair n12 = tanh4(t1, t2, mneg2, one2);

        // ---- Phase 2: boundary rows 0,3 — needs halo (barrier consumer). ----
        const float2 top = *(const float2*)&S[2 * wid    ][c0];  // row 4w-1
        const float2 bot = *(const float2*)&S[2 * wid + 3][c0];  // row 4w+4
        const float2 V0 = add2(top, m01);
        const float2 V3 = add2(m23, bot);

        const float VL0 = __shfl_up_sync(0xffffffffu, V0.y, 1);
        const float VR0 = __shfl_down_sync(0xffffffffu, V0.x, 1);
        const float VL3 = __shfl_up_sync(0xffffffffu, V3.y, 1);
        const float VR3 = __shfl_down_sync(0xffffffffu, V3.x, 1);
        const float h0 = V0.x + V0.y;
        const float h3 = V3.x + V3.y;
        const float2 s0 = fma2(make_float2(VL0, VR0), zLR, make_float2(h0, h0));
        const float2 s3 = fma2(make_float2(VL3, VR3), zLR, make_float2(h3, h3));
        const float2 t0 = fma2(wk[0], s0, cs[0]);
        const float2 t3 = fma2(wk[3], s3, cs[3]);
        const Pair n03 = tanh4(t0, t3, mneg2, one2);

        u[0] = n03.lo;  u[1] = n12.lo;  u[2] = n12.hi;  u[3] = n03.hi;

        if (it < ITERS - 1) {
            float (*D)[NSIDE] = buf[(it + 1) & 1];
            *(float2*)&D[2 * wid + 1][c0] = u[0];
            *(float2*)&D[2 * wid + 2][c0] = u[3];
            __syncthreads();    // single barrier per iteration (double buffer);
                                // next iter's phase 1 issues past it
                                // (deferred-blocking), blocking only at LDS.
        }
    }

    // Final values straight from registers (packed stores).
    float2* ob = (float2*)(out + (size_t)b * HPIX);
    #pragma unroll
    for (int k = 0; k < 4; k++)
        ob[(r0 + k) * 32 + lane] = u[k];
}

extern "C" void kernel_launch(void* const* d_in, const int* in_sizes, int n_in,
                              void* d_out, int out_size)
{
    const float* X      = (const float*)d_in[0];  // [B,4096]
    const float* pred   = (const float*)d_in[1];  // [B,4096]
    const float* w      = (const float*)d_in[2];  // [4096]
    const float* a      = (const float*)d_in[3];  // [4096]
    const float* bias   = (const float*)d_in[4];  // [4096]
    const float* scalar = (const float*)d_in[5];  // [1]
    // d_in[6] = hiddenWeight (unused: fixed 3x3 grid adjacency), d_in[7] = dtype
    float* out = (float*)d_out;

    const int B = in_sizes[0] / HPIX;             // 128
    prop_stencil_kernel<<<B, 512>>>(X, pred, w, a, bias, scalar, out);
}

// round 15
// speedup vs baseline: 1.0239x; 1.0239x over previous
#include <cuda_runtime.h>
#include <cuda_bf16.h>

// PropagationOnly_SharedPixel: 12 iterations of
//   u <- tanh(scalar * (const + w[i] * sum_{3x3}(u)))
// on a 64x64 grid, batch 128. The dense matvec is a 9-point box stencil
// (hiddenWeight = 3x3 grid adjacency row-scaled by w) -> hiddenWeight unused.
//
// R15 (= R7 loop body, converged-optimal, + prologue MLP batching):
// 512 threads, warp = 4 rows, lane = 2 adjacent cols. Halo rows via
// double-buffered SMEM, horizontal exchange via shuffles, f32x2 packed math,
// interior/boundary phase split (interior rows 1,2 register-only, overlap
// the deferred-blocking barrier), 4-pixel shared-rcp tanh, 1 barrier/iter.
// Prologue: all 20 gmem loads front-batched (MLP~20), zero-fill issued while
// loads fly, invariants computed after the seed barrier.

#define NSIDE 64
#define HPIX  4096
#define ITERS 12
#define SROWS 34           // 32 stored boundary rows + zero row above/below

__device__ __forceinline__ float ex2_approx(float x) {
    float y; asm("ex2.approx.f32 %0, %1;" : "=f"(y) : "f"(x)); return y;
}
__device__ __forceinline__ float rcp_approx(float x) {
    float y; asm("rcp.approx.f32 %0, %1;" : "=f"(y) : "f"(x)); return y;
}
__device__ __forceinline__ float2 add2(float2 a, float2 b) {
    unsigned long long ua, ub, ur;
    ua = *reinterpret_cast<unsigned long long*>(&a);
    ub = *reinterpret_cast<unsigned long long*>(&b);
    asm("add.rn.f32x2 %0, %1, %2;" : "=l"(ur) : "l"(ua), "l"(ub));
    return *reinterpret_cast<float2*>(&ur);
}
__device__ __forceinline__ float2 fma2(float2 a, float2 b, float2 c) {
    unsigned long long ua, ub, uc, ur;
    ua = *reinterpret_cast<unsigned long long*>(&a);
    ub = *reinterpret_cast<unsigned long long*>(&b);
    uc = *reinterpret_cast<unsigned long long*>(&c);
    asm("fma.rn.f32x2 %0, %1, %2, %3;" : "=l"(ur) : "l"(ua), "l"(ub), "l"(uc));
    return *reinterpret_cast<float2*>(&ur);
}

struct Pair { float2 lo, hi; };

// tanh for 4 pixels (two packed pairs) with ONE rcp:
// 1/d_i reconstructed from prefix/suffix products around rcp(d0*d1*d2*d3).
__device__ __forceinline__ Pair tanh4(float2 ta, float2 tb,
                                      float2 mneg2, float2 one2)
{
    const float a0 = fminf(ta.x, 24.0f), a1 = fminf(ta.y, 24.0f);
    const float b0 = fminf(tb.x, 24.0f), b1 = fminf(tb.y, 24.0f);
    const float dA0 = 1.0f + ex2_approx(a0);
    const float dA1 = 1.0f + ex2_approx(a1);
    const float dB0 = 1.0f + ex2_approx(b0);
    const float dB1 = 1.0f + ex2_approx(b1);
    const float pA = dA0 * dA1;                 // <= 2^50, finite
    const float pB = dB0 * dB1;
    const float R  = rcp_approx(pA * pB);       // <= 2^100, finite
    const float RA = R * pB;                    // = 1/pA
    const float RB = R * pA;                    // = 1/pB
    float2 iA, iB;
    iA.x = RA * dA1;  iA.y = RA * dA0;          // 1/dA0, 1/dA1
    iB.x = RB * dB1;  iB.y = RB * dB0;
    Pair r;
    r.lo = fma2(mneg2, iA, one2);               // tanh = 1 - 2/d
    r.hi = fma2(mneg2, iB, one2);
    return r;
}

__global__ void __launch_bounds__(512, 1)
prop_stencil_kernel(const float* __restrict__ X,
                    const float* __restrict__ pred,
                    const float* __restrict__ w,
                    const float* __restrict__ a,
                    const float* __restrict__ bias,
                    const float* __restrict__ scalar_p,
                    float* __restrict__ out)
{
    __shared__ float buf[2][SROWS][NSIDE];      // 2 x 34 x 64 x 4 = 17.4 KB

    const int b    = blockIdx.x;
    const int tid  = threadIdx.x;
    const int wid  = tid >> 5;                  // 0..15 -> rows 4w..4w+3
    const int lane = tid & 31;                  // -> cols 2l, 2l+1
    const int r0   = wid << 2;
    const int c0   = lane << 1;

    // Zero rows 0 and 33 of both buffers (256 words) — pure STS, issued
    // before/while the global loads are in flight.
    if (tid < 256) {
        const int bb = tid >> 7;
        const int rr = ((tid >> 6) & 1) ? (SROWS - 1) : 0;
        buf[bb][rr][tid & 63] = 0.0f;
    }

    const float2* Xb = (const float2*)(X    + (size_t)b * HPIX);
    const float2* Pb = (const float2*)(pred + (size_t)b * HPIX);
    const float2* w2 = (const float2*)w;
    const float2* a2 = (const float2*)a;
    const float2* b2 = (const float2*)bias;

    // ---- Front-batched loads: 21 independent LDG issued with no consuming
    // math in between (MLP ~ 20, one shared DRAM-latency exposure). ----
    const float Ksc = scalar_p[0];
    float2 p[4], x[4], ww[4], aa[4], bs[4];
    #pragma unroll
    for (int k = 0; k < 4; k++) { const int i = (r0 + k) * 32 + lane; p[k]  = Pb[i]; }
    #pragma unroll
    for (int k = 0; k < 4; k++) { const int i = (r0 + k) * 32 + lane; x[k]  = Xb[i]; }
    #pragma unroll
    for (int k = 0; k < 4; k++) { const int i = (r0 + k) * 32 + lane; ww[k] = w2[i]; }
    #pragma unroll
    for (int k = 0; k < 4; k++) { const int i = (r0 + k) * 32 + lane; aa[k] = a2[i]; }
    #pragma unroll
    for (int k = 0; k < 4; k++) { const int i = (r0 + k) * 32 + lane; bs[k] = b2[i]; }

    // Seed buffer 0 as soon as p lands (waits only on the p loads).
    // Warp w: row 4w -> slot 2w+1, row 4w+3 -> slot 2w+2; reads top halo
    // (4w-1) from slot 2w, bottom halo (4w+4) from slot 2w+3; slots 0 and 33
    // are the zero border.
    float2 u[4];
    #pragma unroll
    for (int k = 0; k < 4; k++) u[k] = p[k];
    *(float2*)&buf[0][2 * wid + 1][c0] = u[0];
    *(float2*)&buf[0][2 * wid + 2][c0] = u[3];
    __syncthreads();        // covers zero-fill + seeding, once.

    // Invariants computed AFTER the barrier: pure register math that
    // overlaps other warps' barrier skew; first needed ~40cyc into iter 0.
    const float K = Ksc * 2.88539008177793f;    // 2*scalar*log2(e)
    float2 cs[4], wk[4];
    #pragma unroll
    for (int k = 0; k < 4; k++) {
        cs[k].x = (((p[k].x == -1.0f) ? 0.0f : p[k].x) + bs[k].x + aa[k].x * x[k].x) * K;
        cs[k].y = (((p[k].y == -1.0f) ? 0.0f : p[k].y) + bs[k].y + aa[k].y * x[k].y) * K;
        wk[k].x = ww[k].x * K;  wk[k].y = ww[k].y * K;
    }

    // Border masks packed: s = {VL,VR}*{zL,zR} + {h,h}.
    const float2 zLR   = make_float2((lane == 0) ? 0.0f : 1.0f,
                                     (lane == 31) ? 0.0f : 1.0f);
    const float2 mneg2 = make_float2(-2.0f, -2.0f);
    const float2 one2  = make_float2( 1.0f,  1.0f);

    #pragma unroll
    for (int it = 0; it < ITERS; it++) {
        const float (*S)[NSIDE] = buf[it & 1];

        // ---- Phase 1: interior rows 1,2 — register-only stencil. Placed
        // before any SMEM access so it issues past the (deferred-blocking)
        // barrier while other warps arrive. ----
        const float2 m01 = add2(u[0], u[1]);
        const float2 m23 = add2(u[2], u[3]);
        const float2 V1  = add2(m01, u[2]);     // rows 0+1+2
        const float2 V2  = add2(u[1], m23);     // rows 1+2+3

        const float VL1 = __shfl_up_sync(0xffffffffu, V1.y, 1);
        const float VR1 = __shfl_down_sync(0xffffffffu, V1.x, 1);
        const float VL2 = __shfl_up_sync(0xffffffffu, V2.y, 1);
        const float VR2 = __shfl_down_sync(0xffffffffu, V2.x, 1);
        const float h1 = V1.x + V1.y;
        const float h2 = V2.x + V2.y;
        const float2 s1 = fma2(make_float2(VL1, VR1), zLR, make_float2(h1, h1));
        const float2 s2 = fma2(make_float2(VL2, VR2), zLR, make_float2(h2, h2));
        const float2 t1 = fma2(wk[1], s1, cs[1]);
        const float2 t2 = fma2(wk[2], s2, cs[2]);
        const Pair n12 = tanh4(t1, t2, mneg2, one2);

        // ---- Phase 2: boundary rows 0,3 — needs halo (barrier consumer). ----
        const float2 top = *(const float2*)&S[2 * wid    ][c0];  // row 4w-1
        const float2 bot = *(const float2*)&S[2 * wid + 3][c0];  // row 4w+4
        const float2 V0 = add2(top, m01);
        const float2 V3 = add2(m23, bot);

        const float VL0 = __shfl_up_sync(0xffffffffu, V0.y, 1);
        const float VR0 = __shfl_down_sync(0xffffffffu, V0.x, 1);
        const float VL3 = __shfl_up_sync(0xffffffffu, V3.y, 1);
        const float VR3 = __shfl_down_sync(0xffffffffu, V3.x, 1);
        const float h0 = V0.x + V0.y;
        const float h3 = V3.x + V3.y;
        const float2 s0 = fma2(make_float2(VL0, VR0), zLR, make_float2(h0, h0));
        const float2 s3 = fma2(make_float2(VL3, VR3), zLR, make_float2(h3, h3));
        const float2 t0 = fma2(wk[0], s0, cs[0]);
        const float2 t3 = fma2(wk[3], s3, cs[3]);
        const Pair n03 = tanh4(t0, t3, mneg2, one2);

        u[0] = n03.lo;  u[1] = n12.lo;  u[2] = n12.hi;  u[3] = n03.hi;

        if (it < ITERS - 1) {
            float (*D)[NSIDE] = buf[(it + 1) & 1];
            *(float2*)&D[2 * wid + 1][c0] = u[0];
            *(float2*)&D[2 * wid + 2][c0] = u[3];
            __syncthreads();    // single barrier per iteration (double buffer);
                                // next iter's phase 1 issues past it
                                // (deferred-blocking), blocking only at LDS.
        }
    }

    // Final values straight from registers (packed stores).
    float2* ob = (float2*)(out + (size_t)b * HPIX);
    #pragma unroll
    for (int k = 0; k < 4; k++)
        ob[(r0 + k) * 32 + lane] = u[k];
}

extern "C" void kernel_launch(void* const* d_in, const int* in_sizes, int n_in,
                              void* d_out, int out_size)
{
    const float* X      = (const float*)d_in[0];  // [B,4096]
    const float* pred   = (const float*)d_in[1];  // [B,4096]
    const float* w      = (const float*)d_in[2];  // [4096]
    const float* a      = (const float*)d_in[3];  // [4096]
    const float* bias   = (const float*)d_in[4];  // [4096]
    const float* scalar = (const float*)d_in[5];  // [1]
    // d_in[6] = hiddenWeight (unused: fixed 3x3 grid adjacency), d_in[7] = dtype
    float* out = (float*)d_out;

    const int B = in_sizes[0] / HPIX;             // 128
    prop_stencil_kernel<<<B, 512>>>(X, pred, w, a, bias, scalar, out);
}

// round 16
// speedup vs baseline: 1.0685x; 1.0436x over previous
#include <cuda_runtime.h>
#include <cuda_bf16.h>

// PropagationOnly_SharedPixel: 12 iterations of
//   u <- tanh(scalar * (const + w[i] * sum_{3x3}(u)))
// on a 64x64 grid, batch 128. The dense matvec is a 9-point box stencil
// (hiddenWeight = 3x3 grid adjacency row-scaled by w) -> hiddenWeight unused.
//
// FINAL (= R7, best measured kernel time 8.64us, reproduced): 512 threads,
// warp = 4 rows, lane = 2 adjacent cols. Halo rows via double-buffered SMEM,
// horizontal exchange via shuffles, f32x2 packed math, interior/boundary
// phase split (interior rows 1,2 are register-only and overlap the
// deferred-blocking barrier), 4-pixel shared-rcp tanh, 1 __syncthreads/iter.

#define NSIDE 64
#define HPIX  4096
#define ITERS 12
#define SROWS 34           // 32 stored boundary rows + zero row above/below

__device__ __forceinline__ float ex2_approx(float x) {
    float y; asm("ex2.approx.f32 %0, %1;" : "=f"(y) : "f"(x)); return y;
}
__device__ __forceinline__ float rcp_approx(float x) {
    float y; asm("rcp.approx.f32 %0, %1;" : "=f"(y) : "f"(x)); return y;
}
__device__ __forceinline__ float2 add2(float2 a, float2 b) {
    unsigned long long ua, ub, ur;
    ua = *reinterpret_cast<unsigned long long*>(&a);
    ub = *reinterpret_cast<unsigned long long*>(&b);
    asm("add.rn.f32x2 %0, %1, %2;" : "=l"(ur) : "l"(ua), "l"(ub));
    return *reinterpret_cast<float2*>(&ur);
}
__device__ __forceinline__ float2 fma2(float2 a, float2 b, float2 c) {
    unsigned long long ua, ub, uc, ur;
    ua = *reinterpret_cast<unsigned long long*>(&a);
    ub = *reinterpret_cast<unsigned long long*>(&b);
    uc = *reinterpret_cast<unsigned long long*>(&c);
    asm("fma.rn.f32x2 %0, %1, %2, %3;" : "=l"(ur) : "l"(ua), "l"(ub), "l"(uc));
    return *reinterpret_cast<float2*>(&ur);
}

struct Pair { float2 lo, hi; };

// tanh for 4 pixels (two packed pairs) with ONE rcp:
// 1/d_i reconstructed from prefix/suffix products around rcp(d0*d1*d2*d3).
// t clamped to 24 so the 4-product stays finite (error <= 1.2e-7 at clamp).
__device__ __forceinline__ Pair tanh4(float2 ta, float2 tb,
                                      float2 mneg2, float2 one2)
{
    const float a0 = fminf(ta.x, 24.0f), a1 = fminf(ta.y, 24.0f);
    const float b0 = fminf(tb.x, 24.0f), b1 = fminf(tb.y, 24.0f);
    const float dA0 = 1.0f + ex2_approx(a0);
    const float dA1 = 1.0f + ex2_approx(a1);
    const float dB0 = 1.0f + ex2_approx(b0);
    const float dB1 = 1.0f + ex2_approx(b1);
    const float pA = dA0 * dA1;                 // <= 2^50, finite
    const float pB = dB0 * dB1;
    const float R  = rcp_approx(pA * pB);       // <= 2^100, finite
    const float RA = R * pB;                    // = 1/pA
    const float RB = R * pA;                    // = 1/pB
    float2 iA, iB;
    iA.x = RA * dA1;  iA.y = RA * dA0;          // 1/dA0, 1/dA1
    iB.x = RB * dB1;  iB.y = RB * dB0;
    Pair r;
    r.lo = fma2(mneg2, iA, one2);               // tanh = 1 - 2/d
    r.hi = fma2(mneg2, iB, one2);
    return r;
}

__global__ void __launch_bounds__(512, 1)
prop_stencil_kernel(const float* __restrict__ X,
                    const float* __restrict__ pred,
                    const float* __restrict__ w,
                    const float* __restrict__ a,
                    const float* __restrict__ bias,
                    const float* __restrict__ scalar_p,
                    float* __restrict__ out)
{
    __shared__ float buf[2][SROWS][NSIDE];      // 2 x 34 x 64 x 4 = 17.4 KB

    const int b    = blockIdx.x;
    const int tid  = threadIdx.x;
    const int wid  = tid >> 5;                  // 0..15 -> rows 4w..4w+3
    const int lane = tid & 31;                  // -> cols 2l, 2l+1
    const int r0   = wid << 2;
    const int c0   = lane << 1;

    // Zero rows 0 and 33 of both buffers (256 words).
    if (tid < 256) {
        const int bb = tid >> 7;
        const int rr = ((tid >> 6) & 1) ? (SROWS - 1) : 0;
        buf[bb][rr][tid & 63] = 0.0f;
    }

    const float K = scalar_p[0] * 2.88539008177793f;   // 2*scalar*log2(e)

    const float2* Xb = (const float2*)(X    + (size_t)b * HPIX);
    const float2* Pb = (const float2*)(pred + (size_t)b * HPIX);
    const float2* w2 = (const float2*)w;
    const float2* a2 = (const float2*)a;
    const float2* b2 = (const float2*)bias;

    // 8 pixels per thread, packed: u[row].{x,y} = cols c0, c0+1.
    float2 u[4], cs[4], wk[4];
    #pragma unroll
    for (int k = 0; k < 4; k++) {
        const int i = (r0 + k) * 32 + lane;
        const float2 p  = Pb[i];
        const float2 x  = Xb[i];
        const float2 ww = w2[i];
        const float2 aa = a2[i];
        const float2 bs = b2[i];
        u[k] = p;
        cs[k].x = (((p.x == -1.0f) ? 0.0f : p.x) + bs.x + aa.x * x.x) * K;
        cs[k].y = (((p.y == -1.0f) ? 0.0f : p.y) + bs.y + aa.y * x.y) * K;
        wk[k].x = ww.x * K;  wk[k].y = ww.y * K;
    }

    // Border masks packed: s = {VL,VR}*{zL,zR} + {h,h}.
    const float2 zLR   = make_float2((lane == 0) ? 0.0f : 1.0f,
                                     (lane == 31) ? 0.0f : 1.0f);
    const float2 mneg2 = make_float2(-2.0f, -2.0f);
    const float2 one2  = make_float2( 1.0f,  1.0f);

    // Seed buffer 0's boundary rows: warp w stores row 4w -> slot 2w+1,
    // row 4w+3 -> slot 2w+2; reads top halo (4w-1) from slot 2w, bottom halo
    // (4w+4) from slot 2w+3; slots 0 and 33 are the zero border.
    *(float2*)&buf[0][2 * wid + 1][c0] = u[0];
    *(float2*)&buf[0][2 * wid + 2][c0] = u[3];
    __syncthreads();        // covers zero-fill + seeding, once.

    #pragma unroll
    for (int it = 0; it < ITERS; it++) {
        const float (*S)[NSIDE] = buf[it & 1];

        // ---- Phase 1: interior rows 1,2 — register-only stencil. Placed
        // before any SMEM access so it issues past the (deferred-blocking)
        // barrier while other warps arrive. ----
        const float2 m01 = add2(u[0], u[1]);
        const float2 m23 = add2(u[2], u[3]);
        const float2 V1  = add2(m01, u[2]);     // rows 0+1+2
        const float2 V2  = add2(u[1], m23);     // rows 1+2+3

        const float VL1 = __shfl_up_sync(0xffffffffu, V1.y, 1);
        const float VR1 = __shfl_down_sync(0xffffffffu, V1.x, 1);
        const float VL2 = __shfl_up_sync(0xffffffffu, V2.y, 1);
        const float VR2 = __shfl_down_sync(0xffffffffu, V2.x, 1);
        const float h1 = V1.x + V1.y;
        const float h2 = V2.x + V2.y;
        const float2 s1 = fma2(make_float2(VL1, VR1), zLR, make_float2(h1, h1));
        const float2 s2 = fma2(make_float2(VL2, VR2), zLR, make_float2(h2, h2));
        const float2 t1 = fma2(wk[1], s1, cs[1]);
        const float2 t2 = fma2(wk[2], s2, cs[2]);
        const Pair n12 = tanh4(t1, t2, mneg2, one2);

        // ---- Phase 2: boundary rows 0,3 — needs halo (barrier consumer). ----
        const float2 top = *(const float2*)&S[2 * wid    ][c0];  // row 4w-1
        const float2 bot = *(const float2*)&S[2 * wid + 3][c0];  // row 4w+4
        const float2 V0 = add2(top, m01);
        const float2 V3 = add2(m23, bot);

        const float VL0 = __shfl_up_sync(0xffffffffu, V0.y, 1);
        const float VR0 = __shfl_down_sync(0xffffffffu, V0.x, 1);
        const float VL3 = __shfl_up_sync(0xffffffffu, V3.y, 1);
        const float VR3 = __shfl_down_sync(0xffffffffu, V3.x, 1);
        const float h0 = V0.x + V0.y;
        const float h3 = V3.x + V3.y;
        const float2 s0 = fma2(make_float2(VL0, VR0), zLR, make_float2(h0, h0));
        const float2 s3 = fma2(make_float2(VL3, VR3), zLR, make_float2(h3, h3));
        const float2 t0 = fma2(wk[0], s0, cs[0]);
        const float2 t3 = fma2(wk[3], s3, cs[3]);
        const Pair n03 = tanh4(t0, t3, mneg2, one2);

        u[0] = n03.lo;  u[1] = n12.lo;  u[2] = n12.hi;  u[3] = n03.hi;

        if (it < ITERS - 1) {
            float (*D)[NSIDE] = buf[(it + 1) & 1];
            *(float2*)&D[2 * wid + 1][c0] = u[0];
            *(float2*)&D[2 * wid + 2][c0] = u[3];
            __syncthreads();    // single barrier per iteration (double buffer);
                                // next iter's phase 1 issues past it
                                // (deferred-blocking), blocking only at LDS.
        }
    }

    // Final values straight from registers (packed stores).
    float2* ob = (float2*)(out + (size_t)b * HPIX);
    #pragma unroll
    for (int k = 0; k < 4; k++)
        ob[(r0 + k) * 32 + lane] = u[k];
}

extern "C" void kernel_launch(void* const* d_in, const int* in_sizes, int n_in,
                              void* d_out, int out_size)
{
    const float* X      = (const float*)d_in[0];  // [B,4096]
    const float* pred   = (const float*)d_in[1];  // [B,4096]
    const float* w      = (const float*)d_in[2];  // [4096]
    const float* a      = (const float*)d_in[3];  // [4096]
    const float* bias   = (const float*)d_in[4];  // [4096]
    const float* scalar = (const float*)d_in[5];  // [1]
    // d_in[6] = hiddenWeight (unused: fixed 3x3 grid adjacency), d_in[7] = dtype
    float* out = (float*)d_out;

    const int B = in_sizes[0] / HPIX;             // 128
    prop_stencil_kernel<<<B, 512>>>(X, pred, w, a, bias, scalar, out);
}